// round 14
// baseline (speedup 1.0000x reference)
#include <cuda_runtime.h>
#include <cuda_fp16.h>
#include <cstdint>

// Problem constants: B=4, N=512, F=FE=FG=MID=OUT=128
#define BB 4
#define NN 512
#define CC 128
#define AS_STRIDE 132
#define RET_ELEMS (BB*NN*CC)          // 262144

// ---------------- device scratch ----------------
__device__ float g_m1g [BB*NN*CC];              // node@w1+b1 (msgg added in final)
__device__ float g_msg2[BB*NN*CC];
__device__ float g_h1  [BB*NN*CC];
__device__ float g_msgg[BB*CC];
__device__ unsigned g_red[BB*NN*CC];            // zero-init == encoded -inf (encf(x)>0 ∀x)
__device__ int   g_adjflag;
__device__ __half g_wf16[CC*CC];                // W [k][n] fp16

// ---------------- helpers ----------------
__device__ __forceinline__ uint32_t smem_to_u32(const void* p) {
    uint32_t a;
    asm("{ .reg .u64 t; cvta.to.shared.u64 t, %1; cvt.u32.u64 %0, t; }"
        : "=r"(a) : "l"(p));
    return a;
}
__device__ __forceinline__ void ldsm_x4(uint32_t (&r)[4], uint32_t addr) {
    asm volatile("ldmatrix.sync.aligned.m8n8.x4.shared.b16 {%0,%1,%2,%3}, [%4];"
                 : "=r"(r[0]), "=r"(r[1]), "=r"(r[2]), "=r"(r[3]) : "r"(addr));
}
__device__ __forceinline__ void ldsm_x4_t(uint32_t (&r)[4], uint32_t addr) {
    asm volatile("ldmatrix.sync.aligned.m8n8.x4.trans.shared.b16 {%0,%1,%2,%3}, [%4];"
                 : "=r"(r[0]), "=r"(r[1]), "=r"(r[2]), "=r"(r[3]) : "r"(addr));
}
__device__ __forceinline__ void mma_f16(float (&d)[4], const uint32_t (&a)[4],
                                        uint32_t b0, uint32_t b1) {
    asm volatile("mma.sync.aligned.m16n8k16.row.col.f32.f16.f16.f32 "
                 "{%0,%1,%2,%3}, {%4,%5,%6,%7}, {%8,%9}, {%0,%1,%2,%3};"
                 : "+f"(d[0]), "+f"(d[1]), "+f"(d[2]), "+f"(d[3])
                 : "r"(a[0]), "r"(a[1]), "r"(a[2]), "r"(a[3]), "r"(b0), "r"(b1));
}
// order-preserving float<->uint; encf(x) > 0 for all finite x (so 0 == identity)
__device__ __forceinline__ unsigned encf(float f) {
    unsigned u = __float_as_uint(f);
    return (u & 0x80000000u) ? ~u : (u | 0x80000000u);
}
__device__ __forceinline__ float decf(unsigned u) {
    return __uint_as_float((u & 0x80000000u) ? (u & 0x7FFFFFFFu) : ~u);
}
__device__ __forceinline__ unsigned long long fma2(unsigned long long a,
                                                   unsigned long long b,
                                                   unsigned long long c) {
    unsigned long long d;
    asm("fma.rn.f32x2 %0, %1, %2, %3;" : "=l"(d) : "l"(a), "l"(b), "l"(c));
    return d;
}
__device__ __forceinline__ unsigned long long pack2(float x) {
    unsigned long long d;
    asm("mov.b64 %0, {%1, %1};" : "=l"(d) : "f"(x));
    return d;
}
__device__ __forceinline__ float2 unpack2(unsigned long long v) {
    float2 f;
    asm("mov.b64 {%0, %1}, %2;" : "=f"(f.x), "=f"(f.y) : "l"(v));
    return f;
}

// 64-row fp32x2 GEMM core (proj)
__device__ __forceinline__ void gemm_core64(const float* __restrict__ As,
                                            const float* __restrict__ Ws,
                                            unsigned long long acc[4][4],
                                            int tx, int ty)
{
    const float* a0 = As + ty * 4 * AS_STRIDE;
    const float* w0 = Ws + tx * 8;
#pragma unroll 4
    for (int k = 0; k < CC; k++) {
        const ulonglong2 q0 = *(const ulonglong2*)(w0 + k * CC);
        const ulonglong2 q1 = *(const ulonglong2*)(w0 + k * CC + 4);
        const unsigned long long b0 = q0.x, b1 = q0.y, b2 = q1.x, b3 = q1.y;
#pragma unroll
        for (int r = 0; r < 4; r++) {
            const unsigned long long ap = pack2(a0[r * AS_STRIDE + k]);
            acc[r][0] = fma2(ap, b0, acc[r][0]);
            acc[r][1] = fma2(ap, b1, acc[r][1]);
            acc[r][2] = fma2(ap, b2, acc[r][2]);
            acc[r][3] = fma2(ap, b3, acc[r][3]);
        }
    }
}

// shared 64-row proj body (needs CC*CC*4 + 64*AS_STRIDE*4 = 99328 bytes smem)
__device__ __forceinline__ void proj_body(char* smem, int t,
                                          const float* __restrict__ node,
                                          const float* __restrict__ W,
                                          const float* __restrict__ bias,
                                          float* __restrict__ out, int rbase)
{
    float* Ws = (float*)smem;
    float* As = Ws + CC * CC;
    const int tx = t & 15, ty = t >> 4;
    for (int m = t; m < 4096; m += 256)
        *(float4*)(Ws + m * 4) = *(const float4*)(W + m * 4);
    for (int m = t; m < 2048; m += 256) {
        int rr = m >> 5, kk = (m & 31) << 2;
        *(float4*)(As + rr * AS_STRIDE + kk) =
            *(const float4*)(node + (size_t)(rbase + rr) * CC + kk);
    }
    __syncthreads();

    unsigned long long acc[4][4];
#pragma unroll
    for (int r = 0; r < 4; r++)
#pragma unroll
        for (int p = 0; p < 4; p++) acc[r][p] = 0ull;
    gemm_core64(As, Ws, acc, tx, ty);

    float addv[8];
    *(float4*)(addv)     = *(const float4*)(bias + tx * 8);
    *(float4*)(addv + 4) = *(const float4*)(bias + tx * 8 + 4);
#pragma unroll
    for (int r = 0; r < 4; r++) {
        int row = rbase + ty * 4 + r;
        float v[8];
#pragma unroll
        for (int p = 0; p < 4; p++) {
            float2 f = unpack2(acc[r][p]);
            v[2 * p]     = f.x + addv[2 * p];
            v[2 * p + 1] = f.y + addv[2 * p + 1];
        }
        float* op = out + (size_t)row * CC + tx * 8;
        *(float4*)op       = make_float4(v[0], v[1], v[2], v[3]);
        *(float4*)(op + 4) = make_float4(v[4], v[5], v[6], v[7]);
    }
}

// ---------------- noop: keeps launch count/order stable for profiling ----------------
__global__ void noop_kernel() {}

// ================ setup kernel ================
// blk 0: adj detect; 1..64: W fp16 prep; 65..68: msg_g; 69..100: msg2 proj
__global__ __launch_bounds__(256) void setup_kernel(
    const void* __restrict__ adj, const float* __restrict__ w_me,
    const float* __restrict__ graph, const float* __restrict__ w_mg,
    const float* __restrict__ b_mg,
    const float* __restrict__ node,
    const float* __restrict__ w2, const float* __restrict__ bb2)
{
    const int blk = blockIdx.x;
    const int t = threadIdx.x;
    if (blk == 0) {
        __shared__ int cnt[3];
        if (t < 3) cnt[t] = 0;
        __syncthreads();
#pragma unroll
        for (int u = 0; u < 2; u++) {
            size_t d = (size_t)(t + 256 * u) * 513;       // batch-0 diagonal, < 1 MB
            if (((const unsigned char*)adj)[d] == 1) atomicAdd(&cnt[0], 1);
            if (((const int*)adj)[d] == 1)           atomicAdd(&cnt[1], 1);
            if (((const float*)adj)[d] == 1.0f)      atomicAdd(&cnt[2], 1);
        }
        __syncthreads();
        if (t == 0) {
            int f = 0;
            if (cnt[0] == 512) f = 0;
            else if (cnt[1] == 512) f = 1;
            else if (cnt[2] == 512) f = 2;
            g_adjflag = f;
        }
    } else if (blk <= 64) {
        int idx = (blk - 1) * 256 + t;                    // 16384 total
        g_wf16[idx] = __float2half_rn(w_me[idx]);
    } else if (blk <= 68) {
        const int b = blk - 65;
        __shared__ float gr[CC];
        if (t < CC) gr[t] = graph[b * CC + t];
        __syncthreads();
        if (t < CC) {
            float acc = b_mg[t];
#pragma unroll 8
            for (int k = 0; k < CC; k++)
                acc = fmaf(gr[k], w_mg[k * CC + t], acc);
            g_msgg[b * CC + t] = acc;
        }
    } else {
        extern __shared__ char smem[];
        proj_body(smem, t, node, w2, bb2, g_msg2, (blk - 69) * 64);
    }
}

// ======== big kernel: fp16 HMMA GEMM + masked max (blocks 0..4095, i-blocks of 16),
//          plus tail proj blocks for m1g/h1 (blocks 4096..4159) ========
#define ROWSTRIDE 272                 // (128+8)*2 bytes, conflict-free LDSM
#define SM_W    0                     // 128 x 272 fp16 W image (34816)
#define SM_A    (SM_W   + 128*ROWSTRIDE)      // 128 x 272 fp16 A image (34816)
#define SM_MSG2 (SM_A   + 128*ROWSTRIDE)      // 16 x 128 fp32 = 8192
#define SM_PMU  (SM_MSG2 + 16*CC*4)           // 16 x 128 uint = 8192
#define SM_ADJ  (SM_PMU + 16*CC*4)            // 16 x 16 = 256
#define SM_BIAS (SM_ADJ + 256)                // 128 fp32
// allocation also covers proj_body's 99,328-byte layout:
#define SMEM_BIG_T 99328                      // 2 x 99328 -> 2 CTAs/SM

__global__ __launch_bounds__(256, 2) void big_kernel(
    const float* __restrict__ edge, const void* __restrict__ adj,
    const float* __restrict__ b_me, float* __restrict__ out_me,
    const float* __restrict__ node,
    const float* __restrict__ w1, const float* __restrict__ bb1,
    const float* __restrict__ w3, const float* __restrict__ bb3)
{
    extern __shared__ char smem[];
    const int bx  = blockIdx.x;
    const int tid = threadIdx.x;

    // ---- tail proj blocks: m1g (0..31), h1 (32..63) ----
    if (bx >= 4096) {
        const int pidx = bx - 4096;
        const int y = pidx >> 5, px = pidx & 31;
        proj_body(smem, tid,
                  node,
                  y ? w3 : w1, y ? bb3 : bb1,
                  y ? g_h1 : g_m1g, px * 64);
        return;
    }

    const int lane = tid & 31;
    const int wid  = tid >> 5;
    const int warp_m = wid >> 2;      // 0..1  (64 rows each)
    const int warp_n = wid & 3;       // 0..3  (32 cols each)
    const int jt = bx & 31, iblk = (bx >> 5) & 31, b = bx >> 10;
    const int j0 = jt * 16, ibase = iblk * 16;
    const uint32_t sb = smem_to_u32(smem);

    // ---- resident loads ----
    {
        for (int m = tid; m < 2048; m += 256) {            // W fp16 padded image
            int row = m >> 4, q = m & 15;
            *(uint4*)(smem + SM_W + row * ROWSTRIDE + q * 16) =
                ((const uint4*)g_wf16)[row * 16 + q];
        }
        const float4* m2src = (const float4*)(g_msg2 + (((size_t)b * NN + ibase) * CC));
        float4* m2dst = (float4*)(smem + SM_MSG2);
#pragma unroll
        for (int q = 0; q < 2; q++) m2dst[tid + 256 * q] = m2src[tid + 256 * q];

        if (tid < 16) {
            const int flag = g_adjflag;
            const size_t rowoff = (((size_t)b * NN) + ibase + tid) * NN + j0;
            unsigned char* dst = (unsigned char*)(smem + SM_ADJ) + tid * 16;
            if (flag == 0) {
                *(uint4*)dst = *(const uint4*)((const unsigned char*)adj + rowoff);
            } else if (flag == 1) {
                const int* p = (const int*)adj + rowoff;
#pragma unroll
                for (int q = 0; q < 16; q++) dst[q] = (p[q] != 0);
            } else {
                const float* p = (const float*)adj + rowoff;
#pragma unroll
                for (int q = 0; q < 16; q++) dst[q] = (p[q] != 0.0f);
            }
        }
        if (tid < 128) ((float*)(smem + SM_BIAS))[tid] = b_me[tid];
        for (int m = tid; m < 2048; m += 256) ((unsigned*)(smem + SM_PMU))[m] = 0u;
    }

    const float* m2S = (const float*)(smem + SM_MSG2);
    const unsigned char* adjS = (const unsigned char*)(smem + SM_ADJ);
    unsigned* pmu = (unsigned*)(smem + SM_PMU);

    const uint32_t lm_off = (uint32_t)((lane & 15) * ROWSTRIDE + (lane >> 4) * 16);
    const uint32_t a_warp = (uint32_t)(warp_m * 64 * ROWSTRIDE);
    const uint32_t b_warp = (uint32_t)(warp_n * 64);   // 32 cols * 2B

    const int jlA = lane >> 2, jlB = jlA + 8;
    float bc[4][2];
#pragma unroll
    for (int ni = 0; ni < 4; ni++) {
        int c0 = warp_n * 32 + ni * 8 + (lane & 3) * 2;
        bc[ni][0] = b_me[c0]; bc[ni][1] = b_me[c0 + 1];
    }
    __syncthreads();

    float4 ld[4];   // quarter prefetch of next sub-tile

    for (int sub = 0; sub < 2; sub++) {
        const float4* ebase = (const float4*)(edge +
            (((size_t)b * NN + ibase + sub * 8) * NN + j0) * CC);
        const int it0 = (sub == 0) ? 0 : 4;
        if (sub > 0) {
#pragma unroll
            for (int it = 0; it < 4; it++) {
                int m = tid + it * 256;
                int row = m >> 5, c4 = m & 31;
                float4 f = ld[it];
                __half2 hp0(__float2half_rn(f.x), __float2half_rn(f.y));
                __half2 hp1(__float2half_rn(f.z), __float2half_rn(f.w));
                *(uint2*)(smem + SM_A + row * ROWSTRIDE + c4 * 8) =
                    make_uint2(*(uint32_t*)&hp0, *(uint32_t*)&hp1);
            }
        }
#pragma unroll 4
        for (int it = it0; it < 16; it++) {
            int m = tid + it * 256;
            int row = m >> 5, c4 = m & 31;       // row = il*16+jl
            int il = row >> 4, jl = row & 15;
            float4 f = __ldcs(&ebase[((size_t)il * NN + jl) * 32 + c4]);   // stream
            __half2 hp0(__float2half_rn(f.x), __float2half_rn(f.y));
            __half2 hp1(__float2half_rn(f.z), __float2half_rn(f.w));
            *(uint2*)(smem + SM_A + row * ROWSTRIDE + c4 * 8) =
                make_uint2(*(uint32_t*)&hp0, *(uint32_t*)&hp1);
        }
        __syncthreads();

        if (sub < 1) {
            const float4* enext = (const float4*)(edge +
                (((size_t)b * NN + ibase + 8) * NN + j0) * CC);
#pragma unroll
            for (int it = 0; it < 4; it++) {
                int m = tid + it * 256;
                int row = m >> 5, c4 = m & 31;
                int il = row >> 4, jl = row & 15;
                ld[it] = __ldcs(&enext[((size_t)il * NN + jl) * 32 + c4]); // stream
            }
        }

        // ---- single-pass fp16 HMMA ----
        float acc[4][4][4];
#pragma unroll
        for (int mi = 0; mi < 4; mi++)
#pragma unroll
            for (int ni = 0; ni < 4; ni++)
#pragma unroll
                for (int q = 0; q < 4; q++) acc[mi][ni][q] = 0.0f;

        const uint32_t abase = sb + SM_A + a_warp + lm_off;
        const uint32_t bbase = sb + SM_W + b_warp + lm_off;
#pragma unroll
        for (int ks = 0; ks < 8; ks++) {
            uint32_t af[4][4];
            uint32_t bf[2][4];
#pragma unroll
            for (int mi = 0; mi < 4; mi++)
                ldsm_x4(af[mi], abase + mi * 16 * ROWSTRIDE + ks * 32);
#pragma unroll
            for (int nh = 0; nh < 2; nh++)
                ldsm_x4_t(bf[nh], bbase + ks * 16 * ROWSTRIDE + nh * 32);
#pragma unroll
            for (int mi = 0; mi < 4; mi++) {
#pragma unroll
                for (int ni = 0; ni < 4; ni++)
                    mma_f16(acc[mi][ni], af[mi],
                            bf[ni >> 1][(ni & 1) * 2], bf[ni >> 1][(ni & 1) * 2 + 1]);
            }
        }

        // ---- epilogue: bias + streaming STG + masked smem atomicMax ----
#pragma unroll
        for (int mi = 0; mi < 4; mi++) {
            const int il = warp_m * 4 + mi;
            const int ii = sub * 8 + il;
            const bool aA = adjS[ii * 16 + jlA] != 0;
            const bool aB = adjS[ii * 16 + jlB] != 0;
            const float* m2row = m2S + ii * CC;
            float* rowA = out_me + (((size_t)b * NN + ibase + ii) * NN + j0 + jlA) * CC;
            float* rowB = rowA + 8 * CC;
#pragma unroll
            for (int ni = 0; ni < 4; ni++) {
                const int c0 = warp_n * 32 + ni * 8 + (lane & 3) * 2;
                float v0 = acc[mi][ni][0] + bc[ni][0];
                float v1 = acc[mi][ni][1] + bc[ni][1];
                float v2 = acc[mi][ni][2] + bc[ni][0];
                float v3 = acc[mi][ni][3] + bc[ni][1];
                __stcs((float2*)(rowA + c0), make_float2(v0, v1));         // stream
                __stcs((float2*)(rowB + c0), make_float2(v2, v3));         // stream
                if (aA) {
                    atomicMax(&pmu[jlA * CC + c0],     encf(v0 + m2row[c0]));
                    atomicMax(&pmu[jlA * CC + c0 + 1], encf(v1 + m2row[c0 + 1]));
                }
                if (aB) {
                    atomicMax(&pmu[jlB * CC + c0],     encf(v2 + m2row[c0]));
                    atomicMax(&pmu[jlB * CC + c0 + 1], encf(v3 + m2row[c0 + 1]));
                }
            }
        }
        __syncthreads();
    }

    // ---- merge block partials into the global red slab (no-return atomics) ----
    {
        unsigned* rd = g_red + ((size_t)b * NN + j0) * CC;
        for (int m = tid; m < 2048; m += 256) {
            int jl = m >> 7, c = m & 127;
            unsigned pv = pmu[m];
            if (pv) atomicMax(&rd[jl * CC + c], pv);
        }
    }
}

// ---------------- final: red decode + msgg + h2 GEMM + relu (64 blocks x 32 rows) ----------------
__global__ __launch_bounds__(256) void final_kernel(
    const float* __restrict__ w_o2, const float* __restrict__ b_o2,
    float* __restrict__ out_ret)
{
    extern __shared__ char smem[];
    float* Ws = (float*)smem;
    float* As = Ws + CC * CC;

    const int t  = threadIdx.x;
    const int tx = t & 15, ty = t >> 4;
    const int rbase = blockIdx.x * 32;

    for (int m = t; m < 4096; m += 256)
        *(float4*)(Ws + m * 4) = *(const float4*)(w_o2 + m * 4);
    for (int m = t; m < 1024; m += 256) {
        int rr = m >> 5, kk = (m & 31) << 2;
        int row = rbase + rr;
        int b = row >> 9;
        float4 v = *(const float4*)(g_m1g + (size_t)row * CC + kk);
        float4 g = *(const float4*)(g_msgg + b * CC + kk);
        uint4 u = *(const uint4*)(g_red + (size_t)row * CC + kk);
        v.x += g.x + decf(u.x); v.y += g.y + decf(u.y);
        v.z += g.z + decf(u.z); v.w += g.w + decf(u.w);
        *(float4*)(As + rr * AS_STRIDE + kk) = v;
    }
    __syncthreads();

    unsigned long long acc[2][4];
#pragma unroll
    for (int r = 0; r < 2; r++)
#pragma unroll
        for (int p = 0; p < 4; p++) acc[r][p] = 0ull;
    {
        const float* a0 = As + ty * 2 * AS_STRIDE;
        const float* w0 = Ws + tx * 8;
#pragma unroll 4
        for (int k = 0; k < CC; k++) {
            const ulonglong2 q0 = *(const ulonglong2*)(w0 + k * CC);
            const ulonglong2 q1 = *(const ulonglong2*)(w0 + k * CC + 4);
#pragma unroll
            for (int r = 0; r < 2; r++) {
                const unsigned long long ap = pack2(a0[r * AS_STRIDE + k]);
                acc[r][0] = fma2(ap, q0.x, acc[r][0]);
                acc[r][1] = fma2(ap, q0.y, acc[r][1]);
                acc[r][2] = fma2(ap, q1.x, acc[r][2]);
                acc[r][3] = fma2(ap, q1.y, acc[r][3]);
            }
        }
    }

    float bv[8];
    *(float4*)(bv)     = *(const float4*)(b_o2 + tx * 8);
    *(float4*)(bv + 4) = *(const float4*)(b_o2 + tx * 8 + 4);
#pragma unroll
    for (int r = 0; r < 2; r++) {
        int row = rbase + ty * 2 + r;
        const float* h1 = g_h1 + (size_t)row * CC + tx * 8;
        float v[8];
#pragma unroll
        for (int p = 0; p < 4; p++) {
            float2 f = unpack2(acc[r][p]);
            v[2 * p]     = fmaxf(f.x + bv[2 * p]     + h1[2 * p],     0.0f);
            v[2 * p + 1] = fmaxf(f.y + bv[2 * p + 1] + h1[2 * p + 1], 0.0f);
        }
        float* op = out_ret + (size_t)row * CC + tx * 8;
        *(float4*)op       = make_float4(v[0], v[1], v[2], v[3]);
        *(float4*)(op + 4) = make_float4(v[4], v[5], v[6], v[7]);
    }
}

// ---------------- launch ----------------
#define SMEM_SETUP ((CC*CC + 64*AS_STRIDE) * 4)   // 99328
#define SMEM_FIN   ((CC*CC + 32*AS_STRIDE) * 4)   // 82432

extern "C" void kernel_launch(void* const* d_in, const int* in_sizes, int n_in,
                              void* d_out, int out_size) {
    const float* node  = (const float*)d_in[0];
    const float* edge  = (const float*)d_in[1];
    const float* graph = (const float*)d_in[2];
    const void*  adj   = d_in[3];
    // d_in[4] = hidden (unused by reference)
    const float* w_m1 = (const float*)d_in[5];
    const float* b_m1 = (const float*)d_in[6];
    const float* w_m2 = (const float*)d_in[7];
    const float* b_m2 = (const float*)d_in[8];
    const float* w_me = (const float*)d_in[9];
    const float* b_me = (const float*)d_in[10];
    const float* w_mg = (const float*)d_in[11];
    const float* b_mg = (const float*)d_in[12];
    const float* w_o1 = (const float*)d_in[13];
    const float* b_o1 = (const float*)d_in[14];
    const float* w_o2 = (const float*)d_in[15];
    const float* b_o2 = (const float*)d_in[16];

    float* out_ret = (float*)d_out;
    float* out_me  = out_ret + RET_ELEMS;

    cudaFuncSetAttribute(big_kernel,   cudaFuncAttributeMaxDynamicSharedMemorySize, SMEM_BIG_T);
    cudaFuncSetAttribute(setup_kernel, cudaFuncAttributeMaxDynamicSharedMemorySize, SMEM_SETUP);
    cudaFuncSetAttribute(final_kernel, cudaFuncAttributeMaxDynamicSharedMemorySize, SMEM_FIN);

    noop_kernel<<<1, 32>>>();                       // shim: keep big_kernel in slot 4
    setup_kernel<<<101, 256, SMEM_SETUP>>>(adj, w_me, graph, w_mg, b_mg,
                                           node, w_m2, b_m2);
    noop_kernel<<<1, 32>>>();
    big_kernel<<<4160, 256, SMEM_BIG_T>>>(edge, adj, b_me, out_me,
                                          node, w_m1, b_m1, w_o1, b_o1);
    final_kernel<<<64, 256, SMEM_FIN>>>(w_o2, b_o2, out_ret);
}

// round 15
// speedup vs baseline: 1.0569x; 1.0569x over previous
#include <cuda_runtime.h>
#include <cuda_fp16.h>
#include <cstdint>

// Problem constants: B=4, N=512, F=FE=FG=MID=OUT=128
#define BB 4
#define NN 512
#define CC 128
#define AS_STRIDE 132
#define RET_ELEMS (BB*NN*CC)          // 262144
#define NIB 16                        // i-blocks of 32 (512/32)

// ---------------- device scratch ----------------
__device__ float g_m1g [BB*NN*CC];              // node@w1+b1 (msgg added in final)
__device__ float g_msg2[BB*NN*CC];
__device__ float g_h1  [BB*NN*CC];
__device__ float g_msgg[BB*CC];
__device__ unsigned g_red[BB*NN*CC];            // zero-init == encoded -inf (encf(x)>0 ∀x)
__device__ int   g_adjflag;
__device__ __half g_wf16[CC*CC];                // W [k][n] fp16

// ---------------- helpers ----------------
__device__ __forceinline__ uint32_t smem_to_u32(const void* p) {
    uint32_t a;
    asm("{ .reg .u64 t; cvta.to.shared.u64 t, %1; cvt.u32.u64 %0, t; }"
        : "=r"(a) : "l"(p));
    return a;
}
__device__ __forceinline__ void ldsm_x4(uint32_t (&r)[4], uint32_t addr) {
    asm volatile("ldmatrix.sync.aligned.m8n8.x4.shared.b16 {%0,%1,%2,%3}, [%4];"
                 : "=r"(r[0]), "=r"(r[1]), "=r"(r[2]), "=r"(r[3]) : "r"(addr));
}
__device__ __forceinline__ void ldsm_x4_t(uint32_t (&r)[4], uint32_t addr) {
    asm volatile("ldmatrix.sync.aligned.m8n8.x4.trans.shared.b16 {%0,%1,%2,%3}, [%4];"
                 : "=r"(r[0]), "=r"(r[1]), "=r"(r[2]), "=r"(r[3]) : "r"(addr));
}
__device__ __forceinline__ void mma_f16(float (&d)[4], const uint32_t (&a)[4],
                                        uint32_t b0, uint32_t b1) {
    asm volatile("mma.sync.aligned.m16n8k16.row.col.f32.f16.f16.f32 "
                 "{%0,%1,%2,%3}, {%4,%5,%6,%7}, {%8,%9}, {%0,%1,%2,%3};"
                 : "+f"(d[0]), "+f"(d[1]), "+f"(d[2]), "+f"(d[3])
                 : "r"(a[0]), "r"(a[1]), "r"(a[2]), "r"(a[3]), "r"(b0), "r"(b1));
}
// order-preserving float<->uint; encf(x) > 0 for all finite x (so 0 == identity)
__device__ __forceinline__ unsigned encf(float f) {
    unsigned u = __float_as_uint(f);
    return (u & 0x80000000u) ? ~u : (u | 0x80000000u);
}
__device__ __forceinline__ float decf(unsigned u) {
    return __uint_as_float((u & 0x80000000u) ? (u & 0x7FFFFFFFu) : ~u);
}
__device__ __forceinline__ unsigned long long fma2(unsigned long long a,
                                                   unsigned long long b,
                                                   unsigned long long c) {
    unsigned long long d;
    asm("fma.rn.f32x2 %0, %1, %2, %3;" : "=l"(d) : "l"(a), "l"(b), "l"(c));
    return d;
}
__device__ __forceinline__ unsigned long long pack2(float x) {
    unsigned long long d;
    asm("mov.b64 %0, {%1, %1};" : "=l"(d) : "f"(x));
    return d;
}
__device__ __forceinline__ float2 unpack2(unsigned long long v) {
    float2 f;
    asm("mov.b64 {%0, %1}, %2;" : "=f"(f.x), "=f"(f.y) : "l"(v));
    return f;
}

// 64-row fp32x2 GEMM core (proj)
__device__ __forceinline__ void gemm_core64(const float* __restrict__ As,
                                            const float* __restrict__ Ws,
                                            unsigned long long acc[4][4],
                                            int tx, int ty)
{
    const float* a0 = As + ty * 4 * AS_STRIDE;
    const float* w0 = Ws + tx * 8;
#pragma unroll 4
    for (int k = 0; k < CC; k++) {
        const ulonglong2 q0 = *(const ulonglong2*)(w0 + k * CC);
        const ulonglong2 q1 = *(const ulonglong2*)(w0 + k * CC + 4);
        const unsigned long long b0 = q0.x, b1 = q0.y, b2 = q1.x, b3 = q1.y;
#pragma unroll
        for (int r = 0; r < 4; r++) {
            const unsigned long long ap = pack2(a0[r * AS_STRIDE + k]);
            acc[r][0] = fma2(ap, b0, acc[r][0]);
            acc[r][1] = fma2(ap, b1, acc[r][1]);
            acc[r][2] = fma2(ap, b2, acc[r][2]);
            acc[r][3] = fma2(ap, b3, acc[r][3]);
        }
    }
}

// shared 64-row proj body (needs CC*CC*4 + 64*AS_STRIDE*4 = 99328 bytes smem)
__device__ __forceinline__ void proj_body(char* smem, int t,
                                          const float* __restrict__ node,
                                          const float* __restrict__ W,
                                          const float* __restrict__ bias,
                                          float* __restrict__ out, int rbase)
{
    float* Ws = (float*)smem;
    float* As = Ws + CC * CC;
    const int tx = t & 15, ty = t >> 4;
    for (int m = t; m < 4096; m += 256)
        *(float4*)(Ws + m * 4) = *(const float4*)(W + m * 4);
    for (int m = t; m < 2048; m += 256) {
        int rr = m >> 5, kk = (m & 31) << 2;
        *(float4*)(As + rr * AS_STRIDE + kk) =
            *(const float4*)(node + (size_t)(rbase + rr) * CC + kk);
    }
    __syncthreads();

    unsigned long long acc[4][4];
#pragma unroll
    for (int r = 0; r < 4; r++)
#pragma unroll
        for (int p = 0; p < 4; p++) acc[r][p] = 0ull;
    gemm_core64(As, Ws, acc, tx, ty);

    float addv[8];
    *(float4*)(addv)     = *(const float4*)(bias + tx * 8);
    *(float4*)(addv + 4) = *(const float4*)(bias + tx * 8 + 4);
#pragma unroll
    for (int r = 0; r < 4; r++) {
        int row = rbase + ty * 4 + r;
        float v[8];
#pragma unroll
        for (int p = 0; p < 4; p++) {
            float2 f = unpack2(acc[r][p]);
            v[2 * p]     = f.x + addv[2 * p];
            v[2 * p + 1] = f.y + addv[2 * p + 1];
        }
        float* op = out + (size_t)row * CC + tx * 8;
        *(float4*)op       = make_float4(v[0], v[1], v[2], v[3]);
        *(float4*)(op + 4) = make_float4(v[4], v[5], v[6], v[7]);
    }
}

// ---------------- noop: keeps launch count/order stable for profiling ----------------
__global__ void noop_kernel() {}

// ================ setup kernel ================
// blk 0: adj detect; 1..64: W fp16 prep; 65..68: msg_g; 69..100: msg2 proj
__global__ __launch_bounds__(256) void setup_kernel(
    const void* __restrict__ adj, const float* __restrict__ w_me,
    const float* __restrict__ graph, const float* __restrict__ w_mg,
    const float* __restrict__ b_mg,
    const float* __restrict__ node,
    const float* __restrict__ w2, const float* __restrict__ bb2)
{
    const int blk = blockIdx.x;
    const int t = threadIdx.x;
    if (blk == 0) {
        __shared__ int cnt[3];
        if (t < 3) cnt[t] = 0;
        __syncthreads();
#pragma unroll
        for (int u = 0; u < 2; u++) {
            size_t d = (size_t)(t + 256 * u) * 513;       // batch-0 diagonal, < 1 MB
            if (((const unsigned char*)adj)[d] == 1) atomicAdd(&cnt[0], 1);
            if (((const int*)adj)[d] == 1)           atomicAdd(&cnt[1], 1);
            if (((const float*)adj)[d] == 1.0f)      atomicAdd(&cnt[2], 1);
        }
        __syncthreads();
        if (t == 0) {
            int f = 0;
            if (cnt[0] == 512) f = 0;
            else if (cnt[1] == 512) f = 1;
            else if (cnt[2] == 512) f = 2;
            g_adjflag = f;
        }
    } else if (blk <= 64) {
        int idx = (blk - 1) * 256 + t;                    // 16384 total
        g_wf16[idx] = __float2half_rn(w_me[idx]);
    } else if (blk <= 68) {
        const int b = blk - 65;
        __shared__ float gr[CC];
        if (t < CC) gr[t] = graph[b * CC + t];
        __syncthreads();
        if (t < CC) {
            float acc = b_mg[t];
#pragma unroll 8
            for (int k = 0; k < CC; k++)
                acc = fmaf(gr[k], w_mg[k * CC + t], acc);
            g_msgg[b * CC + t] = acc;
        }
    } else {
        extern __shared__ char smem[];
        proj_body(smem, t, node, w2, bb2, g_msg2, (blk - 69) * 64);
    }
}

// ======== big kernel: fp16 HMMA GEMM + masked max (blocks 0..2047, i-blocks of 32),
//          plus tail proj blocks for m1g/h1 (blocks 2048..2111) ========
#define ROWSTRIDE 272                 // (128+8)*2 bytes, conflict-free LDSM
#define SM_W    0                     // 128 x 272 fp16 W image (34816)
#define SM_A    (SM_W   + 128*ROWSTRIDE)      // 128 x 272 fp16 A image (34816)
#define SM_MSG2 (SM_A   + 128*ROWSTRIDE)      // 32 x 128 fp32 = 16384
#define SM_PMU  (SM_MSG2 + 32*CC*4)           // 16 x 128 uint = 8192
#define SM_ADJ  (SM_PMU + 16*CC*4)            // 32 x 16 = 512
#define SM_BIAS (SM_ADJ + 512)                // 128 fp32
// allocation must also cover proj_body's 99,328-byte layout:
#define SMEM_BIG_T 99328                      // 2 x 99328 -> 2 CTAs/SM

__global__ __launch_bounds__(256, 2) void big_kernel(
    const float* __restrict__ edge, const void* __restrict__ adj,
    const float* __restrict__ b_me, float* __restrict__ out_me,
    const float* __restrict__ node,
    const float* __restrict__ w1, const float* __restrict__ bb1,
    const float* __restrict__ w3, const float* __restrict__ bb3)
{
    extern __shared__ char smem[];
    const int bx  = blockIdx.x;
    const int tid = threadIdx.x;

    // ---- tail proj blocks: m1g (0..31), h1 (32..63) ----
    if (bx >= 2048) {
        const int pidx = bx - 2048;
        const int y = pidx >> 5, px = pidx & 31;
        proj_body(smem, tid,
                  node,
                  y ? w3 : w1, y ? bb3 : bb1,
                  y ? g_h1 : g_m1g, px * 64);
        return;
    }

    const int lane = tid & 31;
    const int wid  = tid >> 5;
    const int warp_m = wid >> 2;      // 0..1  (64 rows each)
    const int warp_n = wid & 3;       // 0..3  (32 cols each)
    const int jt = bx & 31, iblk = (bx >> 5) & 15, b = bx >> 9;
    const int j0 = jt * 16, ibase = iblk * 32;
    const uint32_t sb = smem_to_u32(smem);

    // ---- resident loads ----
    {
        for (int m = tid; m < 2048; m += 256) {            // W fp16 padded image
            int row = m >> 4, q = m & 15;
            *(uint4*)(smem + SM_W + row * ROWSTRIDE + q * 16) =
                ((const uint4*)g_wf16)[row * 16 + q];
        }
        const float4* m2src = (const float4*)(g_msg2 + (((size_t)b * NN + ibase) * CC));
        float4* m2dst = (float4*)(smem + SM_MSG2);
#pragma unroll
        for (int q = 0; q < 4; q++) m2dst[tid + 256 * q] = m2src[tid + 256 * q];

        if (tid < 32) {
            const int flag = g_adjflag;
            const size_t rowoff = (((size_t)b * NN) + ibase + tid) * NN + j0;
            unsigned char* dst = (unsigned char*)(smem + SM_ADJ) + tid * 16;
            if (flag == 0) {
                *(uint4*)dst = *(const uint4*)((const unsigned char*)adj + rowoff);
            } else if (flag == 1) {
                const int* p = (const int*)adj + rowoff;
#pragma unroll
                for (int q = 0; q < 16; q++) dst[q] = (p[q] != 0);
            } else {
                const float* p = (const float*)adj + rowoff;
#pragma unroll
                for (int q = 0; q < 16; q++) dst[q] = (p[q] != 0.0f);
            }
        }
        if (tid < 128) ((float*)(smem + SM_BIAS))[tid] = b_me[tid];
        for (int m = tid; m < 2048; m += 256) ((unsigned*)(smem + SM_PMU))[m] = 0u;
    }

    const float* m2S = (const float*)(smem + SM_MSG2);
    const unsigned char* adjS = (const unsigned char*)(smem + SM_ADJ);
    unsigned* pmu = (unsigned*)(smem + SM_PMU);

    const uint32_t lm_off = (uint32_t)((lane & 15) * ROWSTRIDE + (lane >> 4) * 16);
    const uint32_t a_warp = (uint32_t)(warp_m * 64 * ROWSTRIDE);
    const uint32_t b_warp = (uint32_t)(warp_n * 64);   // 32 cols * 2B

    const int jlA = lane >> 2, jlB = jlA + 8;
    float bc[4][2];
#pragma unroll
    for (int ni = 0; ni < 4; ni++) {
        int c0 = warp_n * 32 + ni * 8 + (lane & 3) * 2;
        bc[ni][0] = b_me[c0]; bc[ni][1] = b_me[c0 + 1];
    }
    __syncthreads();

    float4 ld[4];   // quarter prefetch of next sub-tile

    for (int sub = 0; sub < 4; sub++) {
        const float4* ebase = (const float4*)(edge +
            (((size_t)b * NN + ibase + sub * 8) * NN + j0) * CC);
        const int it0 = (sub == 0) ? 0 : 4;
        if (sub > 0) {
#pragma unroll
            for (int it = 0; it < 4; it++) {
                int m = tid + it * 256;
                int row = m >> 5, c4 = m & 31;
                float4 f = ld[it];
                __half2 hp0(__float2half_rn(f.x), __float2half_rn(f.y));
                __half2 hp1(__float2half_rn(f.z), __float2half_rn(f.w));
                *(uint2*)(smem + SM_A + row * ROWSTRIDE + c4 * 8) =
                    make_uint2(*(uint32_t*)&hp0, *(uint32_t*)&hp1);
            }
        }
#pragma unroll 4
        for (int it = it0; it < 16; it++) {
            int m = tid + it * 256;
            int row = m >> 5, c4 = m & 31;       // row = il*16+jl
            int il = row >> 4, jl = row & 15;
            float4 f = __ldcs(&ebase[((size_t)il * NN + jl) * 32 + c4]);   // stream
            __half2 hp0(__float2half_rn(f.x), __float2half_rn(f.y));
            __half2 hp1(__float2half_rn(f.z), __float2half_rn(f.w));
            *(uint2*)(smem + SM_A + row * ROWSTRIDE + c4 * 8) =
                make_uint2(*(uint32_t*)&hp0, *(uint32_t*)&hp1);
        }
        __syncthreads();

        if (sub < 3) {
            const float4* enext = (const float4*)(edge +
                (((size_t)b * NN + ibase + (sub + 1) * 8) * NN + j0) * CC);
#pragma unroll
            for (int it = 0; it < 4; it++) {
                int m = tid + it * 256;
                int row = m >> 5, c4 = m & 31;
                int il = row >> 4, jl = row & 15;
                ld[it] = __ldcs(&enext[((size_t)il * NN + jl) * 32 + c4]); // stream
            }
        }

        // ---- single-pass fp16 HMMA ----
        float acc[4][4][4];
#pragma unroll
        for (int mi = 0; mi < 4; mi++)
#pragma unroll
            for (int ni = 0; ni < 4; ni++)
#pragma unroll
                for (int q = 0; q < 4; q++) acc[mi][ni][q] = 0.0f;

        const uint32_t abase = sb + SM_A + a_warp + lm_off;
        const uint32_t bbase = sb + SM_W + b_warp + lm_off;
#pragma unroll
        for (int ks = 0; ks < 8; ks++) {
            uint32_t af[4][4];
            uint32_t bf[2][4];
#pragma unroll
            for (int mi = 0; mi < 4; mi++)
                ldsm_x4(af[mi], abase + mi * 16 * ROWSTRIDE + ks * 32);
#pragma unroll
            for (int nh = 0; nh < 2; nh++)
                ldsm_x4_t(bf[nh], bbase + ks * 16 * ROWSTRIDE + nh * 32);
#pragma unroll
            for (int mi = 0; mi < 4; mi++) {
#pragma unroll
                for (int ni = 0; ni < 4; ni++)
                    mma_f16(acc[mi][ni], af[mi],
                            bf[ni >> 1][(ni & 1) * 2], bf[ni >> 1][(ni & 1) * 2 + 1]);
            }
        }

        // ---- epilogue: bias + streaming STG + masked smem atomicMax ----
#pragma unroll
        for (int mi = 0; mi < 4; mi++) {
            const int il = warp_m * 4 + mi;
            const int ii = sub * 8 + il;
            const bool aA = adjS[ii * 16 + jlA] != 0;
            const bool aB = adjS[ii * 16 + jlB] != 0;
            const float* m2row = m2S + ii * CC;
            float* rowA = out_me + (((size_t)b * NN + ibase + ii) * NN + j0 + jlA) * CC;
            float* rowB = rowA + 8 * CC;
#pragma unroll
            for (int ni = 0; ni < 4; ni++) {
                const int c0 = warp_n * 32 + ni * 8 + (lane & 3) * 2;
                float v0 = acc[mi][ni][0] + bc[ni][0];
                float v1 = acc[mi][ni][1] + bc[ni][1];
                float v2 = acc[mi][ni][2] + bc[ni][0];
                float v3 = acc[mi][ni][3] + bc[ni][1];
                __stcs((float2*)(rowA + c0), make_float2(v0, v1));         // stream
                __stcs((float2*)(rowB + c0), make_float2(v2, v3));         // stream
                if (aA) {
                    atomicMax(&pmu[jlA * CC + c0],     encf(v0 + m2row[c0]));
                    atomicMax(&pmu[jlA * CC + c0 + 1], encf(v1 + m2row[c0 + 1]));
                }
                if (aB) {
                    atomicMax(&pmu[jlB * CC + c0],     encf(v2 + m2row[c0]));
                    atomicMax(&pmu[jlB * CC + c0 + 1], encf(v3 + m2row[c0 + 1]));
                }
            }
        }
        __syncthreads();
    }

    // ---- merge block partials into the global red slab (no-return atomics) ----
    {
        unsigned* rd = g_red + ((size_t)b * NN + j0) * CC;
        for (int m = tid; m < 2048; m += 256) {
            int jl = m >> 7, c = m & 127;
            unsigned pv = pmu[m];
            if (pv) atomicMax(&rd[jl * CC + c], pv);
        }
    }
}

// ---------------- final: red decode + msgg + h2 GEMM + relu (64 blocks x 32 rows) ----------------
__global__ __launch_bounds__(256) void final_kernel(
    const float* __restrict__ w_o2, const float* __restrict__ b_o2,
    float* __restrict__ out_ret)
{
    extern __shared__ char smem[];
    float* Ws = (float*)smem;
    float* As = Ws + CC * CC;

    const int t  = threadIdx.x;
    const int tx = t & 15, ty = t >> 4;
    const int rbase = blockIdx.x * 32;

    for (int m = t; m < 4096; m += 256)
        *(float4*)(Ws + m * 4) = *(const float4*)(w_o2 + m * 4);
    for (int m = t; m < 1024; m += 256) {
        int rr = m >> 5, kk = (m & 31) << 2;
        int row = rbase + rr;
        int b = row >> 9;
        float4 v = *(const float4*)(g_m1g + (size_t)row * CC + kk);
        float4 g = *(const float4*)(g_msgg + b * CC + kk);
        uint4 u = *(const uint4*)(g_red + (size_t)row * CC + kk);
        v.x += g.x + decf(u.x); v.y += g.y + decf(u.y);
        v.z += g.z + decf(u.z); v.w += g.w + decf(u.w);
        *(float4*)(As + rr * AS_STRIDE + kk) = v;
    }
    __syncthreads();

    unsigned long long acc[2][4];
#pragma unroll
    for (int r = 0; r < 2; r++)
#pragma unroll
        for (int p = 0; p < 4; p++) acc[r][p] = 0ull;
    {
        const float* a0 = As + ty * 2 * AS_STRIDE;
        const float* w0 = Ws + tx * 8;
#pragma unroll 4
        for (int k = 0; k < CC; k++) {
            const ulonglong2 q0 = *(const ulonglong2*)(w0 + k * CC);
            const ulonglong2 q1 = *(const ulonglong2*)(w0 + k * CC + 4);
#pragma unroll
            for (int r = 0; r < 2; r++) {
                const unsigned long long ap = pack2(a0[r * AS_STRIDE + k]);
                acc[r][0] = fma2(ap, q0.x, acc[r][0]);
                acc[r][1] = fma2(ap, q0.y, acc[r][1]);
                acc[r][2] = fma2(ap, q1.x, acc[r][2]);
                acc[r][3] = fma2(ap, q1.y, acc[r][3]);
            }
        }
    }

    float bv[8];
    *(float4*)(bv)     = *(const float4*)(b_o2 + tx * 8);
    *(float4*)(bv + 4) = *(const float4*)(b_o2 + tx * 8 + 4);
#pragma unroll
    for (int r = 0; r < 2; r++) {
        int row = rbase + ty * 2 + r;
        const float* h1 = g_h1 + (size_t)row * CC + tx * 8;
        float v[8];
#pragma unroll
        for (int p = 0; p < 4; p++) {
            float2 f = unpack2(acc[r][p]);
            v[2 * p]     = fmaxf(f.x + bv[2 * p]     + h1[2 * p],     0.0f);
            v[2 * p + 1] = fmaxf(f.y + bv[2 * p + 1] + h1[2 * p + 1], 0.0f);
        }
        float* op = out_ret + (size_t)row * CC + tx * 8;
        *(float4*)op       = make_float4(v[0], v[1], v[2], v[3]);
        *(float4*)(op + 4) = make_float4(v[4], v[5], v[6], v[7]);
    }
}

// ---------------- launch ----------------
#define SMEM_SETUP ((CC*CC + 64*AS_STRIDE) * 4)   // 99328
#define SMEM_FIN   ((CC*CC + 32*AS_STRIDE) * 4)   // 82432

extern "C" void kernel_launch(void* const* d_in, const int* in_sizes, int n_in,
                              void* d_out, int out_size) {
    const float* node  = (const float*)d_in[0];
    const float* edge  = (const float*)d_in[1];
    const float* graph = (const float*)d_in[2];
    const void*  adj   = d_in[3];
    // d_in[4] = hidden (unused by reference)
    const float* w_m1 = (const float*)d_in[5];
    const float* b_m1 = (const float*)d_in[6];
    const float* w_m2 = (const float*)d_in[7];
    const float* b_m2 = (const float*)d_in[8];
    const float* w_me = (const float*)d_in[9];
    const float* b_me = (const float*)d_in[10];
    const float* w_mg = (const float*)d_in[11];
    const float* b_mg = (const float*)d_in[12];
    const float* w_o1 = (const float*)d_in[13];
    const float* b_o1 = (const float*)d_in[14];
    const float* w_o2 = (const float*)d_in[15];
    const float* b_o2 = (const float*)d_in[16];

    float* out_ret = (float*)d_out;
    float* out_me  = out_ret + RET_ELEMS;

    cudaFuncSetAttribute(big_kernel,   cudaFuncAttributeMaxDynamicSharedMemorySize, SMEM_BIG_T);
    cudaFuncSetAttribute(setup_kernel, cudaFuncAttributeMaxDynamicSharedMemorySize, SMEM_SETUP);
    cudaFuncSetAttribute(final_kernel, cudaFuncAttributeMaxDynamicSharedMemorySize, SMEM_FIN);

    noop_kernel<<<1, 32>>>();                       // shim: keep big_kernel in slot 4
    setup_kernel<<<101, 256, SMEM_SETUP>>>(adj, w_me, graph, w_mg, b_mg,
                                           node, w_m2, b_m2);
    noop_kernel<<<1, 32>>>();
    big_kernel<<<2112, 256, SMEM_BIG_T>>>(edge, adj, b_me, out_me,
                                          node, w_m1, b_m1, w_o1, b_o1);
    final_kernel<<<64, 256, SMEM_FIN>>>(w_o2, b_o2, out_ret);
}

// round 16
// speedup vs baseline: 1.0592x; 1.0022x over previous
#include <cuda_runtime.h>
#include <cuda_fp16.h>
#include <cstdint>

// Problem constants: B=4, N=512, F=FE=FG=MID=OUT=128
#define BB 4
#define NN 512
#define CC 128
#define AS_STRIDE 132
#define RET_ELEMS (BB*NN*CC)          // 262144

// ---------------- device scratch ----------------
__device__ float g_m1g [BB*NN*CC];              // node@w1+b1 (msgg added in final)
__device__ float g_msg2[BB*NN*CC];
__device__ float g_h1  [BB*NN*CC];
__device__ float g_msgg[BB*CC];
__device__ unsigned g_red[BB*NN*CC];            // zero-init == encoded -inf (encf(x)>0 ∀x)
__device__ int   g_adjflag;
__device__ __half g_wf16[CC*CC];                // W [k][n] fp16

// ---------------- helpers ----------------
__device__ __forceinline__ uint32_t smem_to_u32(const void* p) {
    uint32_t a;
    asm("{ .reg .u64 t; cvta.to.shared.u64 t, %1; cvt.u32.u64 %0, t; }"
        : "=r"(a) : "l"(p));
    return a;
}
__device__ __forceinline__ void ldsm_x4(uint32_t (&r)[4], uint32_t addr) {
    asm volatile("ldmatrix.sync.aligned.m8n8.x4.shared.b16 {%0,%1,%2,%3}, [%4];"
                 : "=r"(r[0]), "=r"(r[1]), "=r"(r[2]), "=r"(r[3]) : "r"(addr));
}
__device__ __forceinline__ void ldsm_x4_t(uint32_t (&r)[4], uint32_t addr) {
    asm volatile("ldmatrix.sync.aligned.m8n8.x4.trans.shared.b16 {%0,%1,%2,%3}, [%4];"
                 : "=r"(r[0]), "=r"(r[1]), "=r"(r[2]), "=r"(r[3]) : "r"(addr));
}
__device__ __forceinline__ void mma_f16(float (&d)[4], const uint32_t (&a)[4],
                                        uint32_t b0, uint32_t b1) {
    asm volatile("mma.sync.aligned.m16n8k16.row.col.f32.f16.f16.f32 "
                 "{%0,%1,%2,%3}, {%4,%5,%6,%7}, {%8,%9}, {%0,%1,%2,%3};"
                 : "+f"(d[0]), "+f"(d[1]), "+f"(d[2]), "+f"(d[3])
                 : "r"(a[0]), "r"(a[1]), "r"(a[2]), "r"(a[3]), "r"(b0), "r"(b1));
}
// order-preserving float<->uint; encf(x) > 0 for all finite x (so 0 == identity)
__device__ __forceinline__ unsigned encf(float f) {
    unsigned u = __float_as_uint(f);
    return (u & 0x80000000u) ? ~u : (u | 0x80000000u);
}
__device__ __forceinline__ float decf(unsigned u) {
    return __uint_as_float((u & 0x80000000u) ? (u & 0x7FFFFFFFu) : ~u);
}
__device__ __forceinline__ unsigned long long fma2(unsigned long long a,
                                                   unsigned long long b,
                                                   unsigned long long c) {
    unsigned long long d;
    asm("fma.rn.f32x2 %0, %1, %2, %3;" : "=l"(d) : "l"(a), "l"(b), "l"(c));
    return d;
}
__device__ __forceinline__ unsigned long long pack2(float x) {
    unsigned long long d;
    asm("mov.b64 %0, {%1, %1};" : "=l"(d) : "f"(x));
    return d;
}
__device__ __forceinline__ float2 unpack2(unsigned long long v) {
    float2 f;
    asm("mov.b64 {%0, %1}, %2;" : "=f"(f.x), "=f"(f.y) : "l"(v));
    return f;
}

// ---- half-proj body: 64 rows x 64 cols, W slice in smem (needs 66,560 B) ----
// out[rbase+r][cbase+c] = sum_k node[rbase+r][k] * W[k][cbase+c] + bias[cbase+c]
__device__ __forceinline__ void proj_half(char* smem, int t,
                                          const float* __restrict__ node,
                                          const float* __restrict__ W,
                                          const float* __restrict__ bias,
                                          float* __restrict__ out,
                                          int rbase, int cbase)
{
    float* Ws = (float*)smem;                 // 128 k x 64 cols = 32 KB
    float* As = Ws + CC * 64;                 // 64 rows x AS_STRIDE
    const int tx = t & 7, ty = t >> 3;        // tx: 8 col-groups, ty: 0..31 row pairs

    for (int m = t; m < 2048; m += 256) {     // W slice: 128 rows x 16 float4
        int row = m >> 4, c4 = (m & 15) << 2;
        *(float4*)(Ws + row * 64 + c4) = *(const float4*)(W + row * CC + cbase + c4);
    }
    for (int m = t; m < 2048; m += 256) {     // A: 64 rows x 32 float4
        int rr = m >> 5, kk = (m & 31) << 2;
        *(float4*)(As + rr * AS_STRIDE + kk) =
            *(const float4*)(node + (size_t)(rbase + rr) * CC + kk);
    }
    __syncthreads();

    unsigned long long acc[2][4];
#pragma unroll
    for (int r = 0; r < 2; r++)
#pragma unroll
        for (int p = 0; p < 4; p++) acc[r][p] = 0ull;
    {
        const float* a0 = As + ty * 2 * AS_STRIDE;
        const float* w0 = Ws + tx * 8;
#pragma unroll 4
        for (int k = 0; k < CC; k++) {
            const ulonglong2 q0 = *(const ulonglong2*)(w0 + k * 64);
            const ulonglong2 q1 = *(const ulonglong2*)(w0 + k * 64 + 4);
#pragma unroll
            for (int r = 0; r < 2; r++) {
                const unsigned long long ap = pack2(a0[r * AS_STRIDE + k]);
                acc[r][0] = fma2(ap, q0.x, acc[r][0]);
                acc[r][1] = fma2(ap, q0.y, acc[r][1]);
                acc[r][2] = fma2(ap, q1.x, acc[r][2]);
                acc[r][3] = fma2(ap, q1.y, acc[r][3]);
            }
        }
    }

    float addv[8];
    *(float4*)(addv)     = *(const float4*)(bias + cbase + tx * 8);
    *(float4*)(addv + 4) = *(const float4*)(bias + cbase + tx * 8 + 4);
#pragma unroll
    for (int r = 0; r < 2; r++) {
        int row = rbase + ty * 2 + r;
        float v[8];
#pragma unroll
        for (int p = 0; p < 4; p++) {
            float2 f = unpack2(acc[r][p]);
            v[2 * p]     = f.x + addv[2 * p];
            v[2 * p + 1] = f.y + addv[2 * p + 1];
        }
        float* op = out + (size_t)row * CC + cbase + tx * 8;
        *(float4*)op       = make_float4(v[0], v[1], v[2], v[3]);
        *(float4*)(op + 4) = make_float4(v[4], v[5], v[6], v[7]);
    }
}

// ================ setup kernel ================
// blk 0: adj detect; 1..64: W fp16 prep; 65..68: msg_g;
// 69..132: msg2 half-proj (64 blocks: 32 row-tiles x 2 col halves)
__global__ __launch_bounds__(256) void setup_kernel(
    const void* __restrict__ adj, const float* __restrict__ w_me,
    const float* __restrict__ graph, const float* __restrict__ w_mg,
    const float* __restrict__ b_mg,
    const float* __restrict__ node,
    const float* __restrict__ w2, const float* __restrict__ bb2)
{
    const int blk = blockIdx.x;
    const int t = threadIdx.x;
    if (blk == 0) {
        __shared__ int cnt[3];
        if (t < 3) cnt[t] = 0;
        __syncthreads();
#pragma unroll
        for (int u = 0; u < 2; u++) {
            size_t d = (size_t)(t + 256 * u) * 513;       // batch-0 diagonal, < 1 MB
            if (((const unsigned char*)adj)[d] == 1) atomicAdd(&cnt[0], 1);
            if (((const int*)adj)[d] == 1)           atomicAdd(&cnt[1], 1);
            if (((const float*)adj)[d] == 1.0f)      atomicAdd(&cnt[2], 1);
        }
        __syncthreads();
        if (t == 0) {
            int f = 0;
            if (cnt[0] == 512) f = 0;
            else if (cnt[1] == 512) f = 1;
            else if (cnt[2] == 512) f = 2;
            g_adjflag = f;
        }
    } else if (blk <= 64) {
        int idx = (blk - 1) * 256 + t;                    // 16384 total
        g_wf16[idx] = __float2half_rn(w_me[idx]);
    } else if (blk <= 68) {
        const int b = blk - 65;
        __shared__ float gr[CC];
        if (t < CC) gr[t] = graph[b * CC + t];
        __syncthreads();
        if (t < CC) {
            float acc = b_mg[t];
#pragma unroll 8
            for (int k = 0; k < CC; k++)
                acc = fmaf(gr[k], w_mg[k * CC + t], acc);
            g_msgg[b * CC + t] = acc;
        }
    } else {
        extern __shared__ char smem[];
        const int pidx = blk - 69;                        // 0..63
        proj_half(smem, t, node, w2, bb2, g_msg2,
                  (pidx >> 1) * 64, (pidx & 1) * 64);
    }
}

// ======== big kernel: fp16 HMMA GEMM + masked max (blocks 0..2047, i-blocks of 32),
//          plus 128 tail half-proj blocks for m1g/h1 (blocks 2048..2175) ========
#define ROWSTRIDE 272                 // (128+8)*2 bytes, conflict-free LDSM
#define SM_W    0                     // 128 x 272 fp16 W image (34816)
#define SM_A    (SM_W   + 128*ROWSTRIDE)      // 128 x 272 fp16 A image (34816)
#define SM_MSG2 (SM_A   + 128*ROWSTRIDE)      // 32 x 128 fp32 = 16384
#define SM_PMU  (SM_MSG2 + 32*CC*4)           // 16 x 128 uint = 8192
#define SM_ADJ  (SM_PMU + 16*CC*4)            // 32 x 16 = 512
#define SM_BIAS (SM_ADJ + 512)                // 128 fp32
#define SMEM_BIG_T (SM_BIAS + 512)            // 95,232 (covers proj_half's 66,560)

__global__ __launch_bounds__(256, 2) void big_kernel(
    const float* __restrict__ edge, const void* __restrict__ adj,
    const float* __restrict__ b_me, float* __restrict__ out_me,
    const float* __restrict__ node,
    const float* __restrict__ w1, const float* __restrict__ bb1,
    const float* __restrict__ w3, const float* __restrict__ bb3)
{
    extern __shared__ char smem[];
    const int bx  = blockIdx.x;
    const int tid = threadIdx.x;

    // ---- tail half-proj blocks: m1g (0..63), h1 (64..127) ----
    if (bx >= 2048) {
        const int pidx = bx - 2048;
        const int y = pidx >> 6, q = pidx & 63;
        proj_half(smem, tid, node,
                  y ? w3 : w1, y ? bb3 : bb1,
                  y ? g_h1 : g_m1g,
                  (q >> 1) * 64, (q & 1) * 64);
        return;
    }

    const int lane = tid & 31;
    const int wid  = tid >> 5;
    const int warp_m = wid >> 2;      // 0..1  (64 rows each)
    const int warp_n = wid & 3;       // 0..3  (32 cols each)
    const int jt = bx & 31, iblk = (bx >> 5) & 15, b = bx >> 9;
    const int j0 = jt * 16, ibase = iblk * 32;
    const uint32_t sb = smem_to_u32(smem);

    // ---- resident loads ----
    {
        for (int m = tid; m < 2048; m += 256) {            // W fp16 padded image
            int row = m >> 4, q = m & 15;
            *(uint4*)(smem + SM_W + row * ROWSTRIDE + q * 16) =
                ((const uint4*)g_wf16)[row * 16 + q];
        }
        const float4* m2src = (const float4*)(g_msg2 + (((size_t)b * NN + ibase) * CC));
        float4* m2dst = (float4*)(smem + SM_MSG2);
#pragma unroll
        for (int q = 0; q < 4; q++) m2dst[tid + 256 * q] = m2src[tid + 256 * q];

        if (tid < 32) {
            const int flag = g_adjflag;
            const size_t rowoff = (((size_t)b * NN) + ibase + tid) * NN + j0;
            unsigned char* dst = (unsigned char*)(smem + SM_ADJ) + tid * 16;
            if (flag == 0) {
                *(uint4*)dst = *(const uint4*)((const unsigned char*)adj + rowoff);
            } else if (flag == 1) {
                const int* p = (const int*)adj + rowoff;
#pragma unroll
                for (int q = 0; q < 16; q++) dst[q] = (p[q] != 0);
            } else {
                const float* p = (const float*)adj + rowoff;
#pragma unroll
                for (int q = 0; q < 16; q++) dst[q] = (p[q] != 0.0f);
            }
        }
        if (tid < 128) ((float*)(smem + SM_BIAS))[tid] = b_me[tid];
        for (int m = tid; m < 2048; m += 256) ((unsigned*)(smem + SM_PMU))[m] = 0u;
    }

    const float* m2S = (const float*)(smem + SM_MSG2);
    const unsigned char* adjS = (const unsigned char*)(smem + SM_ADJ);
    unsigned* pmu = (unsigned*)(smem + SM_PMU);

    const uint32_t lm_off = (uint32_t)((lane & 15) * ROWSTRIDE + (lane >> 4) * 16);
    const uint32_t a_warp = (uint32_t)(warp_m * 64 * ROWSTRIDE);
    const uint32_t b_warp = (uint32_t)(warp_n * 64);   // 32 cols * 2B

    const int jlA = lane >> 2, jlB = jlA + 8;
    float bc[4][2];
#pragma unroll
    for (int ni = 0; ni < 4; ni++) {
        int c0 = warp_n * 32 + ni * 8 + (lane & 3) * 2;
        bc[ni][0] = b_me[c0]; bc[ni][1] = b_me[c0 + 1];
    }
    __syncthreads();

    float4 ld[4];   // quarter prefetch of next sub-tile

    for (int sub = 0; sub < 4; sub++) {
        const float4* ebase = (const float4*)(edge +
            (((size_t)b * NN + ibase + sub * 8) * NN + j0) * CC);
        const int it0 = (sub == 0) ? 0 : 4;
        if (sub > 0) {
#pragma unroll
            for (int it = 0; it < 4; it++) {
                int m = tid + it * 256;
                int row = m >> 5, c4 = m & 31;
                float4 f = ld[it];
                __half2 hp0(__float2half_rn(f.x), __float2half_rn(f.y));
                __half2 hp1(__float2half_rn(f.z), __float2half_rn(f.w));
                *(uint2*)(smem + SM_A + row * ROWSTRIDE + c4 * 8) =
                    make_uint2(*(uint32_t*)&hp0, *(uint32_t*)&hp1);
            }
        }
#pragma unroll 4
        for (int it = it0; it < 16; it++) {
            int m = tid + it * 256;
            int row = m >> 5, c4 = m & 31;       // row = il*16+jl
            int il = row >> 4, jl = row & 15;
            float4 f = __ldcs(&ebase[((size_t)il * NN + jl) * 32 + c4]);   // stream
            __half2 hp0(__float2half_rn(f.x), __float2half_rn(f.y));
            __half2 hp1(__float2half_rn(f.z), __float2half_rn(f.w));
            *(uint2*)(smem + SM_A + row * ROWSTRIDE + c4 * 8) =
                make_uint2(*(uint32_t*)&hp0, *(uint32_t*)&hp1);
        }
        __syncthreads();

        if (sub < 3) {
            const float4* enext = (const float4*)(edge +
                (((size_t)b * NN + ibase + (sub + 1) * 8) * NN + j0) * CC);
#pragma unroll
            for (int it = 0; it < 4; it++) {
                int m = tid + it * 256;
                int row = m >> 5, c4 = m & 31;
                int il = row >> 4, jl = row & 15;
                ld[it] = __ldcs(&enext[((size_t)il * NN + jl) * 32 + c4]); // stream
            }
        }

        // ---- single-pass fp16 HMMA ----
        float acc[4][4][4];
#pragma unroll
        for (int mi = 0; mi < 4; mi++)
#pragma unroll
            for (int ni = 0; ni < 4; ni++)
#pragma unroll
                for (int q = 0; q < 4; q++) acc[mi][ni][q] = 0.0f;

        const uint32_t abase = sb + SM_A + a_warp + lm_off;
        const uint32_t bbase = sb + SM_W + b_warp + lm_off;
#pragma unroll
        for (int ks = 0; ks < 8; ks++) {
            uint32_t af[4][4];
            uint32_t bf[2][4];
#pragma unroll
            for (int mi = 0; mi < 4; mi++)
                ldsm_x4(af[mi], abase + mi * 16 * ROWSTRIDE + ks * 32);
#pragma unroll
            for (int nh = 0; nh < 2; nh++)
                ldsm_x4_t(bf[nh], bbase + ks * 16 * ROWSTRIDE + nh * 32);
#pragma unroll
            for (int mi = 0; mi < 4; mi++) {
#pragma unroll
                for (int ni = 0; ni < 4; ni++)
                    mma_f16(acc[mi][ni], af[mi],
                            bf[ni >> 1][(ni & 1) * 2], bf[ni >> 1][(ni & 1) * 2 + 1]);
            }
        }

        // ---- epilogue: bias + streaming STG + masked smem atomicMax ----
#pragma unroll
        for (int mi = 0; mi < 4; mi++) {
            const int il = warp_m * 4 + mi;
            const int ii = sub * 8 + il;
            const bool aA = adjS[ii * 16 + jlA] != 0;
            const bool aB = adjS[ii * 16 + jlB] != 0;
            const float* m2row = m2S + ii * CC;
            float* rowA = out_me + (((size_t)b * NN + ibase + ii) * NN + j0 + jlA) * CC;
            float* rowB = rowA + 8 * CC;
#pragma unroll
            for (int ni = 0; ni < 4; ni++) {
                const int c0 = warp_n * 32 + ni * 8 + (lane & 3) * 2;
                float v0 = acc[mi][ni][0] + bc[ni][0];
                float v1 = acc[mi][ni][1] + bc[ni][1];
                float v2 = acc[mi][ni][2] + bc[ni][0];
                float v3 = acc[mi][ni][3] + bc[ni][1];
                __stcs((float2*)(rowA + c0), make_float2(v0, v1));         // stream
                __stcs((float2*)(rowB + c0), make_float2(v2, v3));         // stream
                if (aA) {
                    atomicMax(&pmu[jlA * CC + c0],     encf(v0 + m2row[c0]));
                    atomicMax(&pmu[jlA * CC + c0 + 1], encf(v1 + m2row[c0 + 1]));
                }
                if (aB) {
                    atomicMax(&pmu[jlB * CC + c0],     encf(v2 + m2row[c0]));
                    atomicMax(&pmu[jlB * CC + c0 + 1], encf(v3 + m2row[c0 + 1]));
                }
            }
        }
        __syncthreads();
    }

    // ---- merge block partials into the global red slab (no-return atomics) ----
    {
        unsigned* rd = g_red + ((size_t)b * NN + j0) * CC;
        for (int m = tid; m < 2048; m += 256) {
            int jl = m >> 7, c = m & 127;
            unsigned pv = pmu[m];
            if (pv) atomicMax(&rd[jl * CC + c], pv);
        }
    }
}

// ---------------- final: red decode + msgg + h2 GEMM + relu ----------------
// 128 blocks: (row-tile of 32) x (col half of 64)
__global__ __launch_bounds__(256) void final_kernel(
    const float* __restrict__ w_o2, const float* __restrict__ b_o2,
    float* __restrict__ out_ret)
{
    extern __shared__ char smem[];
    float* Ws = (float*)smem;                 // 128 k x 64 cols = 32 KB
    float* As = Ws + CC * 64;                 // 32 rows x AS_STRIDE

    const int t  = threadIdx.x;
    const int tx = t & 7, ty = t >> 3;        // tx: 8 col groups, ty: 0..31 rows
    const int rbase = (blockIdx.x >> 1) * 32;
    const int cbase = (blockIdx.x & 1) * 64;

    for (int m = t; m < 2048; m += 256) {     // W slice
        int row = m >> 4, c4 = (m & 15) << 2;
        *(float4*)(Ws + row * 64 + c4) = *(const float4*)(w_o2 + row * CC + cbase + c4);
    }
    for (int m = t; m < 1024; m += 256) {     // red rows (full k)
        int rr = m >> 5, kk = (m & 31) << 2;
        int row = rbase + rr;
        int b = row >> 9;
        float4 v = *(const float4*)(g_m1g + (size_t)row * CC + kk);
        float4 g = *(const float4*)(g_msgg + b * CC + kk);
        uint4 u = *(const uint4*)(g_red + (size_t)row * CC + kk);
        v.x += g.x + decf(u.x); v.y += g.y + decf(u.y);
        v.z += g.z + decf(u.z); v.w += g.w + decf(u.w);
        *(float4*)(As + rr * AS_STRIDE + kk) = v;
    }
    __syncthreads();

    unsigned long long acc[4];
#pragma unroll
    for (int p = 0; p < 4; p++) acc[p] = 0ull;
    {
        const float* a0 = As + ty * AS_STRIDE;
        const float* w0 = Ws + tx * 8;
#pragma unroll 4
        for (int k = 0; k < CC; k++) {
            const ulonglong2 q0 = *(const ulonglong2*)(w0 + k * 64);
            const ulonglong2 q1 = *(const ulonglong2*)(w0 + k * 64 + 4);
            const unsigned long long ap = pack2(a0[k]);
            acc[0] = fma2(ap, q0.x, acc[0]);
            acc[1] = fma2(ap, q0.y, acc[1]);
            acc[2] = fma2(ap, q1.x, acc[2]);
            acc[3] = fma2(ap, q1.y, acc[3]);
        }
    }

    float bv[8];
    *(float4*)(bv)     = *(const float4*)(b_o2 + cbase + tx * 8);
    *(float4*)(bv + 4) = *(const float4*)(b_o2 + cbase + tx * 8 + 4);
    const int row = rbase + ty;
    const float* h1 = g_h1 + (size_t)row * CC + cbase + tx * 8;
    float v[8];
#pragma unroll
    for (int p = 0; p < 4; p++) {
        float2 f = unpack2(acc[p]);
        v[2 * p]     = fmaxf(f.x + bv[2 * p]     + h1[2 * p],     0.0f);
        v[2 * p + 1] = fmaxf(f.y + bv[2 * p + 1] + h1[2 * p + 1], 0.0f);
    }
    float* op = out_ret + (size_t)row * CC + cbase + tx * 8;
    *(float4*)op       = make_float4(v[0], v[1], v[2], v[3]);
    *(float4*)(op + 4) = make_float4(v[4], v[5], v[6], v[7]);
}

// ---------------- launch ----------------
#define SMEM_HALF ((CC*64 + 64*AS_STRIDE) * 4)    // 66560 (setup's proj blocks)
#define SMEM_FIN  ((CC*64 + 32*AS_STRIDE) * 4)    // 49664

extern "C" void kernel_launch(void* const* d_in, const int* in_sizes, int n_in,
                              void* d_out, int out_size) {
    const float* node  = (const float*)d_in[0];
    const float* edge  = (const float*)d_in[1];
    const float* graph = (const float*)d_in[2];
    const void*  adj   = d_in[3];
    // d_in[4] = hidden (unused by reference)
    const float* w_m1 = (const float*)d_in[5];
    const float* b_m1 = (const float*)d_in[6];
    const float* w_m2 = (const float*)d_in[7];
    const float* b_m2 = (const float*)d_in[8];
    const float* w_me = (const float*)d_in[9];
    const float* b_me = (const float*)d_in[10];
    const float* w_mg = (const float*)d_in[11];
    const float* b_mg = (const float*)d_in[12];
    const float* w_o1 = (const float*)d_in[13];
    const float* b_o1 = (const float*)d_in[14];
    const float* w_o2 = (const float*)d_in[15];
    const float* b_o2 = (const float*)d_in[16];

    float* out_ret = (float*)d_out;
    float* out_me  = out_ret + RET_ELEMS;

    cudaFuncSetAttribute(big_kernel,   cudaFuncAttributeMaxDynamicSharedMemorySize, SMEM_BIG_T);
    cudaFuncSetAttribute(setup_kernel, cudaFuncAttributeMaxDynamicSharedMemorySize, SMEM_HALF);
    cudaFuncSetAttribute(final_kernel, cudaFuncAttributeMaxDynamicSharedMemorySize, SMEM_FIN);

    setup_kernel<<<133, 256, SMEM_HALF>>>(adj, w_me, graph, w_mg, b_mg,
                                          node, w_m2, b_m2);
    big_kernel<<<2176, 256, SMEM_BIG_T>>>(edge, adj, b_me, out_me,
                                          node, w_m1, b_m1, w_o1, b_o1);
    final_kernel<<<128, 256, SMEM_FIN>>>(w_o2, b_o2, out_ret);
}